// round 8
// baseline (speedup 1.0000x reference)
#include <cuda_runtime.h>
#include <cuda_fp16.h>
#include <cstdint>

// ---------------- problem constants ----------------
#define K_ORIG  20000
#define K_PAD   20032
#define M_TOTAL 2048
#define N_TOTAL 512
#define MT 128
#define NT 128
#define KT 64
#define NCHUNK (K_PAD / KT)          // 313
#define TILES_M (M_TOTAL / MT)       // 16
#define TILES_N (N_TOTAL / NT)       // 4
#define TILES   (TILES_M * TILES_N)  // 64
#define WTOTAL  (TILES * NCHUNK)     // 20032
#define CTAS    148                  // 1 per SM
#define WBASE   (WTOTAL / CTAS)      // 135
#define WREM    (WTOTAL - CTAS * WBASE) // 52

#define A_BYTES (MT * KT * 2)    // 16384
#define B_BYTES (NT * KT * 2)    // 16384
#define STAGE   (A_BYTES + B_BYTES)  // 32768
#define NSTAGE  4
#define SMEM_BYTES (1024 + NSTAGE * STAGE)   // 132096, 1 CTA/SM

// convert grid split
#define XBLOCKS (M_TOTAL * (K_PAD / 4) / 256)          // 40064
#define EKB     (K_PAD / 32)                           // 626
#define EBLOCKS (EKB * (N_TOTAL / 32))                 // 10016

// ---------------- device scratch (fp16 operands) ----------------
__device__ __half g_xh[(size_t)M_TOTAL * K_PAD];   // x   [M, K_PAD] row-major
__device__ __half g_eh[(size_t)N_TOTAL * K_PAD];   // E^T [N, K_PAD] K-major

// ---------------- helpers ----------------
__device__ __forceinline__ uint32_t smem_u32(const void* p) {
    uint32_t a;
    asm("{ .reg .u64 t; cvta.to.shared.u64 t, %1; cvt.u32.u64 %0, t; }"
        : "=r"(a) : "l"(p));
    return a;
}

__device__ __forceinline__ uint32_t swz(uint32_t off) {
    return off ^ ((off >> 3) & 0x70u);     // 128B-period XOR swizzle
}

__device__ __forceinline__ void cp16(uint32_t sa, const void* gp) {
    asm volatile("cp.async.cg.shared.global [%0], [%1], 16;" :: "r"(sa), "l"(gp));
}

__device__ __forceinline__ void ldsm4(uint32_t* r, uint32_t sa) {
    asm volatile("ldmatrix.sync.aligned.m8n8.x4.shared.b16 {%0,%1,%2,%3}, [%4];"
                 : "=r"(r[0]), "=r"(r[1]), "=r"(r[2]), "=r"(r[3]) : "r"(sa));
}

__device__ __forceinline__ void mma16816(float* d, const uint32_t* a,
                                         const uint32_t* b) {
    asm volatile(
        "mma.sync.aligned.m16n8k16.row.col.f32.f16.f16.f32 "
        "{%0,%1,%2,%3}, {%4,%5,%6,%7}, {%8,%9}, {%0,%1,%2,%3};"
        : "+f"(d[0]), "+f"(d[1]), "+f"(d[2]), "+f"(d[3])
        : "r"(a[0]), "r"(a[1]), "r"(a[2]), "r"(a[3]), "r"(b[0]), "r"(b[1]));
}

// ---------------- combined conversion kernel ----------------
__global__ void convert_all_kernel(const float* __restrict__ x,
                                   const float* __restrict__ e) {
    __shared__ float tile[32][33];
    if (blockIdx.x < XBLOCKS) {
        // x fp32 [M, 20000] -> fp16 [M, 20032] (zero-padded tail)
        unsigned idx4 = blockIdx.x * 256u + threadIdx.x;
        const unsigned per_row = K_PAD / 4;             // 5008
        unsigned m = idx4 / per_row;
        unsigned k = (idx4 - m * per_row) * 4u;
        float4 v;
        if (k + 3 < K_ORIG) {
            v = *reinterpret_cast<const float4*>(x + (size_t)m * K_ORIG + k);
        } else {
            v.x = v.y = v.z = v.w = 0.0f;
        }
        __half2 h0 = __floats2half2_rn(v.x, v.y);
        __half2 h1 = __floats2half2_rn(v.z, v.w);
        uint2 pk;
        pk.x = *reinterpret_cast<uint32_t*>(&h0);
        pk.y = *reinterpret_cast<uint32_t*>(&h1);
        *reinterpret_cast<uint2*>(g_xh + (size_t)m * K_PAD + k) = pk;
    } else {
        // E fp32 [20000, 512] -> E^T fp16 [512, 20032] K-major, zero-padded
        const int b  = blockIdx.x - XBLOCKS;
        const int kb = (b % EKB) * 32;
        const int hb = (b / EKB) * 32;
        const int tx = threadIdx.x & 31;
        const int ty = threadIdx.x >> 5;       // 0..7
        #pragma unroll
        for (int i = ty; i < 32; i += 8) {
            int k = kb + i;
            tile[i][tx] = (k < K_ORIG) ? e[(size_t)k * N_TOTAL + hb + tx] : 0.0f;
        }
        __syncthreads();
        #pragma unroll
        for (int i = ty; i < 32; i += 8) {
            int h = hb + i;
            int k = kb + tx;
            g_eh[(size_t)h * K_PAD + k] = __float2half_rn(tile[tx][i]);
        }
    }
}

// ---------------- stream-K fp16 mma.sync GEMM, 128x128 CTA tile ----------
// out[m, n] = (sum_k x[m,k] * E[k,n]) / K_ORIG + bias[n]  (RED-accumulated)
__global__ void __launch_bounds__(512, 1)
gemm_streamk_kernel(const float* __restrict__ bias, float* __restrict__ out) {
    extern __shared__ char smem_raw[];
    uint32_t sb = smem_u32(smem_raw);
    sb = (sb + 1023u) & ~1023u;

    const int tid = threadIdx.x;
    const int wid = tid >> 5;
    const int lid = tid & 31;

    // ---- work range ----
    const int bi   = blockIdx.x;
    const int wbeg = bi * WBASE + (bi < WREM ? bi : WREM);
    const int CN   = WBASE + (bi < WREM ? 1 : 0);

    int ct = wbeg / NCHUNK;        // consumer tile
    int cc = wbeg - ct * NCHUNK;   // consumer chunk within tile
    int pt = ct, pc = cc;          // prefetch tile/chunk

    // ---- producer indexing: 512 threads, 16B each ----
    const int c16 = tid & 7;
    const int r64 = tid >> 3;      // 0..63

    auto load_next = [&](int il) {
        const uint32_t st = sb + (uint32_t)(il & (NSTAGE - 1)) * (uint32_t)STAGE;
        const int k0 = pc * KT;
        const __half* xg = g_xh + (size_t)((pt >> 2) * MT) * K_PAD;
        const __half* eg = g_eh + (size_t)((pt & 3) * NT) * K_PAD;
        #pragma unroll
        for (int i = 0; i < 2; i++) {          // A: 128 rows
            const int row = r64 + i * 64;
            const uint32_t sa = st + swz((uint32_t)(row * 128 + c16 * 16));
            cp16(sa, xg + (size_t)row * K_PAD + (k0 + c16 * 8));
        }
        #pragma unroll
        for (int i = 0; i < 2; i++) {          // B: 128 rows
            const int row = r64 + i * 64;
            const uint32_t sa = st + (uint32_t)A_BYTES
                              + swz((uint32_t)(row * 128 + c16 * 16));
            cp16(sa, eg + (size_t)row * K_PAD + (k0 + c16 * 8));
        }
        asm volatile("cp.async.commit_group;" ::: "memory");
        if (++pc == NCHUNK) { pc = 0; pt++; }
    };

    // ---- consumer indexing: 16 warps as 4 (M) x 4 (N), warp tile 32x32 ----
    const int wm = wid & 3;
    const int wn = wid >> 2;
    const int mbase = wm * 32;
    const int nbase = wn * 32;
    const int a_row = mbase + (lid & 15);
    const uint32_t a_kh = (uint32_t)(lid >> 4) * 16u;
    const int b_row = nbase + ((lid >> 4) * 8) + (lid & 7);
    const uint32_t b_kh = (uint32_t)((lid >> 3) & 1) * 16u;

    float acc[2][4][4];
    #pragma unroll
    for (int i = 0; i < 2; i++)
        #pragma unroll
        for (int j = 0; j < 4; j++)
            #pragma unroll
            for (int q = 0; q < 4; q++) acc[i][j][q] = 0.0f;

    const float inv = 1.0f / (float)K_ORIG;
    const int erow = mbase + (lid >> 2);
    const int ecol = nbase + (lid & 3) * 2;

    auto epilogue = [&](int t, bool addb) {
        const int m0 = (t >> 2) * MT;
        const int n0 = (t & 3) * NT;
        #pragma unroll
        for (int im = 0; im < 2; im++) {
            #pragma unroll
            for (int in = 0; in < 4; in++) {
                const int m = m0 + erow + im * 16;
                const int n = n0 + ecol + in * 8;
                const float b0 = addb ? __ldg(&bias[n]) : 0.0f;
                const float b1 = addb ? __ldg(&bias[n + 1]) : 0.0f;
                atomicAdd(&out[(size_t)m * N_TOTAL + n],           acc[im][in][0] * inv + b0);
                atomicAdd(&out[(size_t)m * N_TOTAL + n + 1],       acc[im][in][1] * inv + b1);
                atomicAdd(&out[(size_t)(m + 8) * N_TOTAL + n],     acc[im][in][2] * inv + b0);
                atomicAdd(&out[(size_t)(m + 8) * N_TOTAL + n + 1], acc[im][in][3] * inv + b1);
                acc[im][in][0] = 0.0f; acc[im][in][1] = 0.0f;
                acc[im][in][2] = 0.0f; acc[im][in][3] = 0.0f;
            }
        }
    };

    // ---- preamble: 3 chunks in flight ----
    load_next(0);
    if (CN > 1) load_next(1);
    if (CN > 2) load_next(2);

    bool addb = (cc == 0);     // this CTA owns chunk 0 of tile ct?

    for (int il = 0; il < CN; il++) {
        if (il + 2 < CN) {
            asm volatile("cp.async.wait_group 2;" ::: "memory");
        } else if (il + 1 < CN) {
            asm volatile("cp.async.wait_group 1;" ::: "memory");
        } else {
            asm volatile("cp.async.wait_group 0;" ::: "memory");
        }
        __syncthreads();

        if (il + 3 < CN) load_next(il + 3);

        const uint32_t st = sb + (uint32_t)(il & (NSTAGE - 1)) * (uint32_t)STAGE;
        #pragma unroll
        for (int ks = 0; ks < 4; ks++) {
            const uint32_t kb = (uint32_t)ks * 32u;
            uint32_t af[2][4];
            #pragma unroll
            for (int im = 0; im < 2; im++) {
                const uint32_t off = (uint32_t)((a_row + im * 16) * 128) + kb + a_kh;
                ldsm4(af[im], st + swz(off));
            }
            uint32_t bf[2][4];
            #pragma unroll
            for (int ib = 0; ib < 2; ib++) {
                const uint32_t off = (uint32_t)((b_row + ib * 16) * 128) + kb + b_kh;
                ldsm4(bf[ib], st + (uint32_t)A_BYTES + swz(off));
            }
            #pragma unroll
            for (int im = 0; im < 2; im++) {
                #pragma unroll
                for (int in = 0; in < 4; in++) {
                    mma16816(acc[im][in], af[im], &bf[in >> 1][(in & 1) * 2]);
                }
            }
        }

        // tile boundary or end of range -> flush partial
        if (cc == NCHUNK - 1 || il == CN - 1) {
            epilogue(ct, addb);
            ct++; cc = 0; addb = true;
        } else {
            cc++;
        }
    }
}

// ---------------- launch ----------------
extern "C" void kernel_launch(void* const* d_in, const int* in_sizes, int n_in,
                              void* d_out, int out_size) {
    (void)in_sizes; (void)n_in;
    const float* x    = (const float*)d_in[0];
    const float* e    = (const float*)d_in[1];
    const float* bias = (const float*)d_in[2];
    float* out = (float*)d_out;

    cudaFuncSetAttribute(gemm_streamk_kernel,
                         cudaFuncAttributeMaxDynamicSharedMemorySize, SMEM_BYTES);

    cudaMemsetAsync(out, 0, (size_t)out_size * sizeof(float), 0);
    convert_all_kernel<<<XBLOCKS + EBLOCKS, 256>>>(x, e);
    gemm_streamk_kernel<<<CTAS, 512, SMEM_BYTES>>>(bias, out);
}

// round 9
// speedup vs baseline: 1.1443x; 1.1443x over previous
#include <cuda_runtime.h>
#include <cuda_fp16.h>
#include <cstdint>

// ---------------- problem constants ----------------
#define K_ORIG  20000
#define K_PAD   20032
#define M_TOTAL 2048
#define N_TOTAL 512
#define MT 128
#define NT 128
#define KT 64
#define NCHUNK (K_PAD / KT)          // 313
#define TILES_M (M_TOTAL / MT)       // 16
#define TILES_N (N_TOTAL / NT)       // 4
#define TILES   (TILES_M * TILES_N)  // 64
#define WTOTAL  (TILES * NCHUNK)     // 20032
#define CTAS    296                  // 148 SMs x 2
#define WBASE   (WTOTAL / CTAS)      // 67
#define WREM    (WTOTAL - CTAS * WBASE) // 200

#define A_BYTES (MT * KT * 2)    // 16384
#define B_BYTES (NT * KT * 2)    // 16384
#define STAGE   (A_BYTES + B_BYTES)  // 32768
#define NSTAGE  3
#define SMEM_BYTES (1024 + NSTAGE * STAGE)   // 99328 -> 2 CTAs/SM

// convert grid split
#define XBLOCKS (M_TOTAL * (K_PAD / 4) / 256)          // 40064
#define EKB     (K_PAD / 32)                           // 626
#define EBLOCKS (EKB * (N_TOTAL / 32))                 // 10016

// ---------------- device scratch (fp16 operands) ----------------
__device__ __half g_xh[(size_t)M_TOTAL * K_PAD];   // x   [M, K_PAD] row-major
__device__ __half g_eh[(size_t)N_TOTAL * K_PAD];   // E^T [N, K_PAD] K-major

// ---------------- helpers ----------------
__device__ __forceinline__ uint32_t smem_u32(const void* p) {
    uint32_t a;
    asm("{ .reg .u64 t; cvta.to.shared.u64 t, %1; cvt.u32.u64 %0, t; }"
        : "=r"(a) : "l"(p));
    return a;
}

__device__ __forceinline__ uint32_t swz(uint32_t off) {
    return off ^ ((off >> 3) & 0x70u);     // 128B-period XOR swizzle
}

__device__ __forceinline__ void cp16(uint32_t sa, const void* gp) {
    asm volatile("cp.async.cg.shared.global [%0], [%1], 16;" :: "r"(sa), "l"(gp));
}

__device__ __forceinline__ void ldsm4(uint32_t* r, uint32_t sa) {
    asm volatile("ldmatrix.sync.aligned.m8n8.x4.shared.b16 {%0,%1,%2,%3}, [%4];"
                 : "=r"(r[0]), "=r"(r[1]), "=r"(r[2]), "=r"(r[3]) : "r"(sa));
}

__device__ __forceinline__ void mma16816(float* d, const uint32_t* a,
                                         const uint32_t* b) {
    asm volatile(
        "mma.sync.aligned.m16n8k16.row.col.f32.f16.f16.f32 "
        "{%0,%1,%2,%3}, {%4,%5,%6,%7}, {%8,%9}, {%0,%1,%2,%3};"
        : "+f"(d[0]), "+f"(d[1]), "+f"(d[2]), "+f"(d[3])
        : "r"(a[0]), "r"(a[1]), "r"(a[2]), "r"(a[3]), "r"(b[0]), "r"(b[1]));
}

// ---------------- combined conversion kernel ----------------
__global__ void convert_all_kernel(const float* __restrict__ x,
                                   const float* __restrict__ e) {
    __shared__ float tile[32][33];
    if (blockIdx.x < XBLOCKS) {
        // x fp32 [M, 20000] -> fp16 [M, 20032] (zero-padded tail)
        unsigned idx4 = blockIdx.x * 256u + threadIdx.x;
        const unsigned per_row = K_PAD / 4;             // 5008
        unsigned m = idx4 / per_row;
        unsigned k = (idx4 - m * per_row) * 4u;
        float4 v;
        if (k + 3 < K_ORIG) {
            v = *reinterpret_cast<const float4*>(x + (size_t)m * K_ORIG + k);
        } else {
            v.x = v.y = v.z = v.w = 0.0f;
        }
        __half2 h0 = __floats2half2_rn(v.x, v.y);
        __half2 h1 = __floats2half2_rn(v.z, v.w);
        uint2 pk;
        pk.x = *reinterpret_cast<uint32_t*>(&h0);
        pk.y = *reinterpret_cast<uint32_t*>(&h1);
        *reinterpret_cast<uint2*>(g_xh + (size_t)m * K_PAD + k) = pk;
    } else {
        // E fp32 [20000, 512] -> E^T fp16 [512, 20032] K-major, zero-padded
        const int b  = blockIdx.x - XBLOCKS;
        const int kb = (b % EKB) * 32;
        const int hb = (b / EKB) * 32;
        const int tx = threadIdx.x & 31;
        const int ty = threadIdx.x >> 5;       // 0..7
        #pragma unroll
        for (int i = ty; i < 32; i += 8) {
            int k = kb + i;
            tile[i][tx] = (k < K_ORIG) ? e[(size_t)k * N_TOTAL + hb + tx] : 0.0f;
        }
        __syncthreads();
        #pragma unroll
        for (int i = ty; i < 32; i += 8) {
            int h = hb + i;
            int k = kb + tx;
            g_eh[(size_t)h * K_PAD + k] = __float2half_rn(tile[tx][i]);
        }
    }
}

// ---------------- stream-K fp16 GEMM: 128x128 CTA, 256 thr, warp 64x32 ----
// out[m, n] = (sum_k x[m,k] * E[k,n]) / K_ORIG + bias[n]  (RED-accumulated)
__global__ void __launch_bounds__(256, 2)
gemm_streamk_kernel(const float* __restrict__ bias, float* __restrict__ out) {
    extern __shared__ char smem_raw[];
    uint32_t sb = smem_u32(smem_raw);
    sb = (sb + 1023u) & ~1023u;

    const int tid = threadIdx.x;
    const int wid = tid >> 5;
    const int lid = tid & 31;

    // ---- work range ----
    const int bi   = blockIdx.x;
    const int wbeg = bi * WBASE + (bi < WREM ? bi : WREM);
    const int CN   = WBASE + (bi < WREM ? 1 : 0);

    int ct = wbeg / NCHUNK;        // consumer tile
    int cc = wbeg - ct * NCHUNK;   // consumer chunk within tile
    int pt = ct, pc = cc;          // prefetch tile/chunk

    // ---- producer indexing: 256 threads, 4x16B A + 4x16B B each ----
    const int c16 = tid & 7;
    const int r32 = tid >> 3;      // 0..31

    auto load_next = [&](int il) {
        const uint32_t st = sb + (uint32_t)(il % NSTAGE) * (uint32_t)STAGE;
        const int k0 = pc * KT;
        const __half* xg = g_xh + (size_t)((pt >> 2) * MT) * K_PAD;
        const __half* eg = g_eh + (size_t)((pt & 3) * NT) * K_PAD;
        #pragma unroll
        for (int i = 0; i < 4; i++) {          // A: 128 rows
            const int row = r32 + i * 32;
            const uint32_t sa = st + swz((uint32_t)(row * 128 + c16 * 16));
            cp16(sa, xg + (size_t)row * K_PAD + (k0 + c16 * 8));
        }
        #pragma unroll
        for (int i = 0; i < 4; i++) {          // B: 128 rows
            const int row = r32 + i * 32;
            const uint32_t sa = st + (uint32_t)A_BYTES
                              + swz((uint32_t)(row * 128 + c16 * 16));
            cp16(sa, eg + (size_t)row * K_PAD + (k0 + c16 * 8));
        }
        asm volatile("cp.async.commit_group;" ::: "memory");
        if (++pc == NCHUNK) { pc = 0; pt++; }
    };

    // ---- consumer indexing: 8 warps as 2 (M) x 4 (N), warp tile 64x32 ----
    const int wm = wid & 1;
    const int wn = wid >> 1;
    const int mbase = wm * 64;
    const int nbase = wn * 32;
    const int a_row = mbase + (lid & 15);
    const uint32_t a_kh = (uint32_t)(lid >> 4) * 16u;
    const int b_row = nbase + ((lid >> 4) * 8) + (lid & 7);
    const uint32_t b_kh = (uint32_t)((lid >> 3) & 1) * 16u;

    float acc[4][4][4];
    #pragma unroll
    for (int i = 0; i < 4; i++)
        #pragma unroll
        for (int j = 0; j < 4; j++)
            #pragma unroll
            for (int q = 0; q < 4; q++) acc[i][j][q] = 0.0f;

    const float inv = 1.0f / (float)K_ORIG;
    const int erow = mbase + (lid >> 2);
    const int ecol = nbase + (lid & 3) * 2;

    auto epilogue = [&](int t, bool addb) {
        const int m0 = (t >> 2) * MT;
        const int n0 = (t & 3) * NT;
        #pragma unroll
        for (int im = 0; im < 4; im++) {
            #pragma unroll
            for (int in = 0; in < 4; in++) {
                const int m = m0 + erow + im * 16;
                const int n = n0 + ecol + in * 8;
                const float b0 = addb ? __ldg(&bias[n]) : 0.0f;
                const float b1 = addb ? __ldg(&bias[n + 1]) : 0.0f;
                atomicAdd(&out[(size_t)m * N_TOTAL + n],           acc[im][in][0] * inv + b0);
                atomicAdd(&out[(size_t)m * N_TOTAL + n + 1],       acc[im][in][1] * inv + b1);
                atomicAdd(&out[(size_t)(m + 8) * N_TOTAL + n],     acc[im][in][2] * inv + b0);
                atomicAdd(&out[(size_t)(m + 8) * N_TOTAL + n + 1], acc[im][in][3] * inv + b1);
                acc[im][in][0] = 0.0f; acc[im][in][1] = 0.0f;
                acc[im][in][2] = 0.0f; acc[im][in][3] = 0.0f;
            }
        }
    };

    // ---- preamble: 2 chunks in flight (3 stages, depth 2) ----
    load_next(0);
    if (CN > 1) load_next(1);

    bool addb = (cc == 0);     // this CTA owns chunk 0 of tile ct?

    for (int il = 0; il < CN; il++) {
        if (il + 1 < CN) {
            asm volatile("cp.async.wait_group 1;" ::: "memory");
        } else {
            asm volatile("cp.async.wait_group 0;" ::: "memory");
        }
        __syncthreads();

        if (il + 2 < CN) load_next(il + 2);

        const uint32_t st = sb + (uint32_t)(il % NSTAGE) * (uint32_t)STAGE;
        #pragma unroll
        for (int ks = 0; ks < 4; ks++) {
            const uint32_t kb = (uint32_t)ks * 32u;
            uint32_t af[4][4];
            #pragma unroll
            for (int im = 0; im < 4; im++) {
                const uint32_t off = (uint32_t)((a_row + im * 16) * 128) + kb + a_kh;
                ldsm4(af[im], st + swz(off));
            }
            uint32_t bf[2][4];
            #pragma unroll
            for (int ib = 0; ib < 2; ib++) {
                const uint32_t off = (uint32_t)((b_row + ib * 16) * 128) + kb + b_kh;
                ldsm4(bf[ib], st + (uint32_t)A_BYTES + swz(off));
            }
            #pragma unroll
            for (int im = 0; im < 4; im++) {
                #pragma unroll
                for (int in = 0; in < 4; in++) {
                    mma16816(acc[im][in], af[im], &bf[in >> 1][(in & 1) * 2]);
                }
            }
        }

        // tile boundary or end of range -> flush partial
        if (cc == NCHUNK - 1 || il == CN - 1) {
            epilogue(ct, addb);
            ct++; cc = 0; addb = true;
        } else {
            cc++;
        }
    }
}

// ---------------- launch ----------------
extern "C" void kernel_launch(void* const* d_in, const int* in_sizes, int n_in,
                              void* d_out, int out_size) {
    (void)in_sizes; (void)n_in;
    const float* x    = (const float*)d_in[0];
    const float* e    = (const float*)d_in[1];
    const float* bias = (const float*)d_in[2];
    float* out = (float*)d_out;

    cudaFuncSetAttribute(gemm_streamk_kernel,
                         cudaFuncAttributeMaxDynamicSharedMemorySize, SMEM_BYTES);

    cudaMemsetAsync(out, 0, (size_t)out_size * sizeof(float), 0);
    convert_all_kernel<<<XBLOCKS + EBLOCKS, 256>>>(x, e);
    gemm_streamk_kernel<<<CTAS, 256, SMEM_BYTES>>>(bias, out);
}